// round 12
// baseline (speedup 1.0000x reference)
#include <cuda_runtime.h>
#include <cuda_fp16.h>
#include <cstdint>

#define B_      8
#define N_SEQ   1024
#define DIM     448
#define HEADS   7
#define DHEAD   64
#define INNER   448
// 0.125 * log2(e)
#define SCALE_C 0.18033688011114633f

// scratch (R8-validated formats)
__device__ float  g_q    [B_ * HEADS * N_SEQ * DHEAD]; // tf32 bits (float), pre-scaled
__device__ __half g_vt   [B_ * HEADS * DHEAD * N_SEQ]; // fp16, [b,h,d,m]
__device__ float  g_att  [B_ * N_SEQ * INNER];         // tf32 bits (float)
__device__ float  g_x32  [B_ * N_SEQ * DIM];           // tf32(x)
__device__ float  g_wqv32[DIM * 2 * INNER];            // tf32(w_qv)
__device__ float  g_k32  [HEADS * N_SEQ * DHEAD];      // tf32(ext_k)
__device__ float  g_wout32[DIM * DIM];                 // tf32(w_out)

// ---------------------------------------------------------------------------
__device__ __forceinline__ uint32_t f2tf32(float f) {
    uint32_t r;
    asm("cvt.rna.tf32.f32 %0, %1;" : "=r"(r) : "f"(f));
    return r;
}

__device__ __forceinline__ float ex2(float x) {
    float y;
    asm("ex2.approx.ftz.f32 %0, %1;" : "=f"(y) : "f"(x));
    return y;
}

// pack two f32 into f16x2: lo -> lower half, hi -> upper half
__device__ __forceinline__ uint32_t pack_f16(float lo, float hi) {
    uint32_t d;
    asm("cvt.rn.f16x2.f32 %0, %1, %2;" : "=r"(d) : "f"(hi), "f"(lo));
    return d;
}

__device__ __forceinline__ void mma_tf32(float c[4],
    uint32_t a0, uint32_t a1, uint32_t a2, uint32_t a3,
    uint32_t b0, uint32_t b1)
{
    asm volatile(
        "mma.sync.aligned.m16n8k8.row.col.f32.tf32.tf32.f32 "
        "{%0,%1,%2,%3}, {%4,%5,%6,%7}, {%8,%9}, {%0,%1,%2,%3};"
        : "+f"(c[0]), "+f"(c[1]), "+f"(c[2]), "+f"(c[3])
        : "r"(a0), "r"(a1), "r"(a2), "r"(a3), "r"(b0), "r"(b1));
}

__device__ __forceinline__ void mma_f16(float c[4],
    uint32_t a0, uint32_t a1, uint32_t a2, uint32_t a3,
    uint32_t b0, uint32_t b1)
{
    asm volatile(
        "mma.sync.aligned.m16n8k16.row.col.f32.f16.f16.f32 "
        "{%0,%1,%2,%3}, {%4,%5,%6,%7}, {%8,%9}, {%0,%1,%2,%3};"
        : "+f"(c[0]), "+f"(c[1]), "+f"(c[2]), "+f"(c[3])
        : "r"(a0), "r"(a1), "r"(a2), "r"(a3), "r"(b0), "r"(b1));
}

__device__ __forceinline__ void cp_async16(uint32_t smem_addr, const void* gptr) {
    asm volatile("cp.async.ca.shared.global [%0], [%1], 16;"
                 :: "r"(smem_addr), "l"(gptr));
}

// ---------------------------------------------------------------------------
// prep: convert x, w_qv, ext_k, w_out to tf32 once (memory-bound) — R8 verbatim
// ---------------------------------------------------------------------------
#define N4_X    (B_ * N_SEQ * DIM / 4)
#define N4_WQV  (DIM * 2 * INNER / 4)
#define N4_K    (HEADS * N_SEQ * DHEAD / 4)
#define N4_WOUT (DIM * DIM / 4)
#define N4_TOT  (N4_X + N4_WQV + N4_K + N4_WOUT)

__global__ void __launch_bounds__(256) cvt_all_kernel(
    const float* __restrict__ x, const float* __restrict__ wqv,
    const float* __restrict__ ek, const float* __restrict__ wout)
{
    int i = blockIdx.x * 256 + threadIdx.x;
    const float4* src;
    uint4* dst;
    if (i < N4_X)                     { src = (const float4*)x    + i;                           dst = (uint4*)g_x32    + i; }
    else if (i < N4_X + N4_WQV)       { i -= N4_X;                src = (const float4*)wqv + i;  dst = (uint4*)g_wqv32  + i; }
    else if (i < N4_X + N4_WQV + N4_K){ i -= N4_X + N4_WQV;       src = (const float4*)ek  + i;  dst = (uint4*)g_k32    + i; }
    else                              { i -= N4_X + N4_WQV + N4_K; src = (const float4*)wout + i; dst = (uint4*)g_wout32 + i; }
    const float4 v = *src;
    uint4 u;
    u.x = f2tf32(v.x); u.y = f2tf32(v.y);
    u.z = f2tf32(v.z); u.w = f2tf32(v.w);
    *dst = u;
}

// ---------------------------------------------------------------------------
// tf32 GEMM — R8 verbatim (R5 form: single-buffer + reg prefetch).
// EPI=0: q (tf32 float, scaled) -> g_q, v (fp16, [d][m]) -> g_vt
// EPI=1: A=g_att (tf32), W=g_wout32, +bias -> out (fp32)
// ---------------------------------------------------------------------------
#define GBM 128
#define GBN 64
#define GBK 32
#define SA_STR 36
#define SB2_STR 72

template<int EPI>
__global__ void __launch_bounds__(256) gemm_tf32_kernel(
    const float* __restrict__ bias, float* __restrict__ out, int N)
{
    __shared__ uint32_t sA[GBM * SA_STR];
    __shared__ uint32_t sB[GBK * SB2_STR];

    const float* A = (EPI == 1) ? (const float*)g_att : (const float*)g_x32;
    const float* W = (EPI == 1) ? (const float*)g_wout32 : (const float*)g_wqv32;

    const int tid  = threadIdx.x;
    const int wid  = tid >> 5, lane = tid & 31;
    const int lr   = lane >> 2, lc = lane & 3;
    const int wm   = wid >> 1, wn = wid & 1;
    const int m0   = wm * 32, n0w = wn * 32;
    const int row0 = blockIdx.y * GBM;
    const int col0 = blockIdx.x * GBN;

    const int a_row = tid >> 3, a_k4 = tid & 7;
    const int b_kr = tid >> 4, b_n4 = tid & 15;

    float acc[2][4][4];
    #pragma unroll
    for (int i = 0; i < 2; ++i)
        #pragma unroll
        for (int j = 0; j < 4; ++j)
            #pragma unroll
            for (int e = 0; e < 4; ++e) acc[i][j][e] = 0.f;

    uint4 ra[4], rb[2];
    #pragma unroll
    for (int it = 0; it < 4; ++it)
        ra[it] = *(const uint4*)(A + (row0 + a_row + 32 * it) * DIM + a_k4 * 4);
    #pragma unroll
    for (int it = 0; it < 2; ++it)
        rb[it] = *(const uint4*)(W + (b_kr + 16 * it) * N + col0 + b_n4 * 4);

    for (int k0 = 0; k0 < DIM; k0 += GBK) {
        #pragma unroll
        for (int it = 0; it < 4; ++it)
            *(uint4*)(sA + (a_row + 32 * it) * SA_STR + a_k4 * 4) = ra[it];
        #pragma unroll
        for (int it = 0; it < 2; ++it)
            *(uint4*)(sB + (b_kr + 16 * it) * SB2_STR + b_n4 * 4) = rb[it];
        __syncthreads();

        if (k0 + GBK < DIM) {
            #pragma unroll
            for (int it = 0; it < 4; ++it)
                ra[it] = *(const uint4*)(A + (row0 + a_row + 32 * it) * DIM + k0 + GBK + a_k4 * 4);
            #pragma unroll
            for (int it = 0; it < 2; ++it)
                rb[it] = *(const uint4*)(W + (k0 + GBK + b_kr + 16 * it) * N + col0 + b_n4 * 4);
        }

        #pragma unroll
        for (int kk = 0; kk < 4; ++kk) {
            const int kb = kk * 8;
            uint32_t af[2][4], bf[4][2];
            #pragma unroll
            for (int i = 0; i < 2; ++i) {
                const int mr = m0 + i * 16 + lr;
                af[i][0] = sA[ mr      * SA_STR + kb + lc    ];
                af[i][1] = sA[(mr + 8) * SA_STR + kb + lc    ];
                af[i][2] = sA[ mr      * SA_STR + kb + lc + 4];
                af[i][3] = sA[(mr + 8) * SA_STR + kb + lc + 4];
            }
            #pragma unroll
            for (int j = 0; j < 4; ++j) {
                const int nc = n0w + j * 8 + lr;
                bf[j][0] = sB[(kb + lc    ) * SB2_STR + nc];
                bf[j][1] = sB[(kb + lc + 4) * SB2_STR + nc];
            }
            #pragma unroll
            for (int i = 0; i < 2; ++i)
                #pragma unroll
                for (int j = 0; j < 4; ++j)
                    mma_tf32(acc[i][j], af[i][0], af[i][1], af[i][2], af[i][3],
                             bf[j][0], bf[j][1]);
        }
        __syncthreads();
    }

    if (EPI == 0) {
        if (col0 < INNER) {
            const int h = col0 >> 6;
            #pragma unroll
            for (int i = 0; i < 2; ++i) {
                #pragma unroll
                for (int half = 0; half < 2; ++half) {
                    const int rg = row0 + m0 + i * 16 + lr + half * 8;
                    const int bb = rg >> 10, nn = rg & 1023;
                    float* rp = g_q + ((((bb * HEADS + h) << 10) + nn) << 6);
                    #pragma unroll
                    for (int j = 0; j < 4; ++j) {
                        const int d = n0w + j * 8 + lc * 2;
                        float2 o;
                        o.x = __int_as_float(f2tf32(acc[i][j][half * 2]     * SCALE_C));
                        o.y = __int_as_float(f2tf32(acc[i][j][half * 2 + 1] * SCALE_C));
                        *(float2*)(rp + d) = o;
                    }
                }
            }
        } else {
            const int h = (col0 - INNER) >> 6;
            #pragma unroll
            for (int i = 0; i < 2; ++i) {
                #pragma unroll
                for (int half = 0; half < 2; ++half) {
                    const int rg = row0 + m0 + i * 16 + lr + half * 8;
                    const int bb = rg >> 10, nn = rg & 1023;
                    __half* vp = g_vt + (((bb * HEADS + h) << 6) << 10) + nn;
                    #pragma unroll
                    for (int j = 0; j < 4; ++j) {
                        const int d = n0w + j * 8 + lc * 2;
                        vp[ d      << 10] = __float2half_rn(acc[i][j][half * 2]);
                        vp[(d + 1) << 10] = __float2half_rn(acc[i][j][half * 2 + 1]);
                    }
                }
            }
        }
    } else {
        #pragma unroll
        for (int i = 0; i < 2; ++i) {
            #pragma unroll
            for (int half = 0; half < 2; ++half) {
                const int rg = row0 + m0 + i * 16 + lr + half * 8;
                float* rp = out + rg * DIM + col0;
                #pragma unroll
                for (int j = 0; j < 4; ++j) {
                    const int c = n0w + j * 8 + lc * 2;
                    float2 o;
                    o.x = acc[i][j][half * 2]     + bias[col0 + c];
                    o.y = acc[i][j][half * 2 + 1] + bias[col0 + c + 1];
                    *(float2*)(rp + c) = o;
                }
            }
        }
    }
}

// ---------------------------------------------------------------------------
// Fused attention — R8 per-warp code, but BM=128 (256 threads, 8 warps):
// each K/V tile + barrier pair now serves 128 rows. Q staging overlays the
// K/V buffers via a union (Q is register-resident before first K load).
// tf32 QK, ex2.approx softmax (no max), register fp16 P, fp16 PV.
// ---------------------------------------------------------------------------
#define BM 128
#define BN 64
#define SK_STR 68
#define SVT_STR 36
#define SQ_STR 68

__global__ void __launch_bounds__(256) attn_mma_kernel(
    const float* __restrict__ BIAS)
{
    __shared__ union SMem {
        struct {
            alignas(16) uint32_t k [BN * SK_STR];      // K tile tf32
            alignas(16) uint32_t vt[DHEAD * SVT_STR];  // V^T tile fp16
        } kv;
        alignas(16) uint32_t q[BM * SQ_STR];           // Q staging (prologue only)
    } sm;

    const int tid  = threadIdx.x;
    const int wid  = tid >> 5, lane = tid & 31;
    const int bb = blockIdx.x, qt = blockIdx.y, h = blockIdx.z;

    const int lr = lane >> 2;
    const int lc = lane & 3;
    const int r0 = wid * 16 + lr;     // 0..127

    const uint32_t sk_u  = (uint32_t)__cvta_generic_to_shared(sm.kv.k);
    const uint32_t svt_u = (uint32_t)__cvta_generic_to_shared(sm.kv.vt);

    // ---- stage Q (tf32 float, pre-scaled) through sm.q, pull A-fragments
    const uint4* Qg = (const uint4*)(g_q + (((bb * HEADS + h) << 10) + qt * BM) * 64);
    #pragma unroll
    for (int i = tid; i < BM * 16; i += 256) {
        const int row = i >> 4, c4 = i & 15;
        *(uint4*)(sm.q + row * SQ_STR + c4 * 4) = Qg[row * 16 + c4];
    }
    __syncthreads();

    uint32_t qa[8][4];
    #pragma unroll
    for (int ks = 0; ks < 8; ++ks) {
        qa[ks][0] = sm.q[ r0      * SQ_STR + ks * 8 + lc    ];
        qa[ks][1] = sm.q[(r0 + 8) * SQ_STR + ks * 8 + lc    ];
        qa[ks][2] = sm.q[ r0      * SQ_STR + ks * 8 + lc + 4];
        qa[ks][3] = sm.q[(r0 + 8) * SQ_STR + ks * 8 + lc + 4];
    }
    __syncthreads();   // Q staging dead; union space reused for K/V below

    float acc[8][4];
    #pragma unroll
    for (int nt = 0; nt < 8; ++nt)
        #pragma unroll
        for (int j = 0; j < 4; ++j) acc[nt][j] = 0.f;

    float l_lo = 0.f, l_hi = 0.f;

    const uint4* Kg = (const uint4*)(g_k32 + ((h << 10) << 6));
    const __half* Vtg = g_vt + (((bb * HEADS + h) << 6) << 10);
    const float* Bg = BIAS + (((h << 10) + qt * BM) << 10);
    const float* bl = Bg +  r0      * N_SEQ + lc * 2;
    const float* bh = Bg + (r0 + 8) * N_SEQ + lc * 2;

    for (int mt = 0; mt < N_SEQ; mt += BN) {
        // ---- cp.async: K (tf32) and V^T (fp16), 256 threads
        #pragma unroll
        for (int i = tid; i < BN * 16; i += 256) {
            const int row = i >> 4, c4 = i & 15;
            cp_async16(sk_u + (row * SK_STR + c4 * 4) * 4, Kg + (mt + row) * 16 + c4);
        }
        #pragma unroll
        for (int i = tid; i < DHEAD * 8; i += 256) {
            const int row = i >> 3, c = i & 7;
            cp_async16(svt_u + (row * SVT_STR + c * 4) * 4, Vtg + (row << 10) + mt + c * 8);
        }
        // ---- bias into registers (overlaps cp.async)
        float2 blo[8], bhi[8];
        #pragma unroll
        for (int nt = 0; nt < 8; ++nt) {
            blo[nt] = *(const float2*)(bl + mt + nt * 8);
            bhi[nt] = *(const float2*)(bh + mt + nt * 8);
        }
        asm volatile("cp.async.wait_all;" ::: "memory");
        __syncthreads();

        // ---- S = Q @ K^T (tf32)
        float s[8][4];
        #pragma unroll
        for (int nt = 0; nt < 8; ++nt)
            #pragma unroll
            for (int j = 0; j < 4; ++j) s[nt][j] = 0.f;

        #pragma unroll
        for (int nt = 0; nt < 8; ++nt) {
            const int n0 = nt * 8;
            #pragma unroll
            for (int ks = 0; ks < 8; ++ks) {
                const uint32_t b0 = sm.kv.k[(n0 + lr) * SK_STR + ks * 8 + lc    ];
                const uint32_t b1 = sm.kv.k[(n0 + lr) * SK_STR + ks * 8 + lc + 4];
                mma_tf32(s[nt], qa[ks][0], qa[ks][1], qa[ks][2], qa[ks][3], b0, b1);
            }
        }

        // ---- p = exp2(s + bias*scale); pack fp16 in regs (A-frag layout)
        uint32_t pa[8][2];
        #pragma unroll
        for (int nt = 0; nt < 8; ++nt) {
            const float p0 = ex2(fmaf(blo[nt].x, SCALE_C, s[nt][0]));
            const float p1 = ex2(fmaf(blo[nt].y, SCALE_C, s[nt][1]));
            const float p2 = ex2(fmaf(bhi[nt].x, SCALE_C, s[nt][2]));
            const float p3 = ex2(fmaf(bhi[nt].y, SCALE_C, s[nt][3]));
            l_lo += p0 + p1;
            l_hi += p2 + p3;
            pa[nt][0] = pack_f16(p0, p1);   // rows lr
            pa[nt][1] = pack_f16(p2, p3);   // rows lr+8
        }

        // ---- acc += P @ V (fp16 m16n8k16, P register-direct)
        #pragma unroll
        for (int ks = 0; ks < 4; ++ks) {
            const uint32_t a0 = pa[2 * ks    ][0];
            const uint32_t a1 = pa[2 * ks    ][1];
            const uint32_t a2 = pa[2 * ks + 1][0];
            const uint32_t a3 = pa[2 * ks + 1][1];
            #pragma unroll
            for (int nt = 0; nt < 8; ++nt) {
                const uint32_t* vrow = sm.kv.vt + (nt * 8 + lr) * SVT_STR + ks * 8;
                mma_f16(acc[nt], a0, a1, a2, a3, vrow[lc], vrow[lc + 4]);
            }
        }
        __syncthreads();   // all K/Vt reads done before next tile's cp.async
    }

    // ---- row-sum reduce, normalize, write tf32 float (R8-validated format)
    l_lo += __shfl_xor_sync(0xffffffffu, l_lo, 1);
    l_lo += __shfl_xor_sync(0xffffffffu, l_lo, 2);
    l_hi += __shfl_xor_sync(0xffffffffu, l_hi, 1);
    l_hi += __shfl_xor_sync(0xffffffffu, l_hi, 2);
    const float inv_lo = 1.f / l_lo;
    const float inv_hi = 1.f / l_hi;
    const int n_lo = qt * BM + r0;
    float* outb = g_att + ((bb << 10) * INNER) + (h << 6);
    #pragma unroll
    for (int nt = 0; nt < 8; ++nt) {
        const int d = nt * 8 + lc * 2;
        float2 olo, ohi;
        olo.x = __int_as_float(f2tf32(acc[nt][0] * inv_lo));
        olo.y = __int_as_float(f2tf32(acc[nt][1] * inv_lo));
        ohi.x = __int_as_float(f2tf32(acc[nt][2] * inv_hi));
        ohi.y = __int_as_float(f2tf32(acc[nt][3] * inv_hi));
        *(float2*)(outb + n_lo       * INNER + d) = olo;
        *(float2*)(outb + (n_lo + 8) * INNER + d) = ohi;
    }
}

// ---------------------------------------------------------------------------
extern "C" void kernel_launch(void* const* d_in, const int* in_sizes, int n_in,
                              void* d_out, int out_size)
{
    const float* x        = (const float*)d_in[0];
    const float* w_qv     = (const float*)d_in[1];
    const float* ext_k    = (const float*)d_in[2];
    const float* ext_bias = (const float*)d_in[3];
    const float* w_out    = (const float*)d_in[4];
    const float* b_out    = (const float*)d_in[5];
    float* out = (float*)d_out;

    cvt_all_kernel<<<N4_TOT / 256, 256>>>(x, w_qv, ext_k, w_out);
    gemm_tf32_kernel<0><<<dim3(2 * INNER / GBN, B_ * N_SEQ / GBM), 256>>>(
        nullptr, nullptr, 2 * INNER);
    attn_mma_kernel<<<dim3(B_, N_SEQ / BM, HEADS), 256>>>(ext_bias);
    gemm_tf32_kernel<1><<<dim3(DIM / GBN, B_ * N_SEQ / GBM), 256>>>(
        b_out, out, DIM);
}

// round 13
// speedup vs baseline: 1.3360x; 1.3360x over previous
#include <cuda_runtime.h>
#include <cuda_fp16.h>
#include <cstdint>

#define B_      8
#define N_SEQ   1024
#define DIM     448
#define HEADS   7
#define DHEAD   64
#define INNER   448
// 0.125 * log2(e)
#define SCALE_C 0.18033688011114633f

// scratch
__device__ __align__(16) __half g_q16 [B_ * HEADS * N_SEQ * DHEAD]; // fp16, pre-scaled
__device__ __align__(16) __half g_k16 [HEADS * N_SEQ * DHEAD];      // fp16(ext_k)
__device__ __align__(16) __half g_vt  [B_ * HEADS * DHEAD * N_SEQ]; // fp16, [b,h,d,m]
__device__ float  g_att  [B_ * N_SEQ * INNER];         // tf32 bits (float)
__device__ float  g_x32  [B_ * N_SEQ * DIM];           // tf32(x)
__device__ float  g_wqv32[DIM * 2 * INNER];            // tf32(w_qv)
__device__ float  g_wout32[DIM * DIM];                 // tf32(w_out)

// ---------------------------------------------------------------------------
__device__ __forceinline__ uint32_t f2tf32(float f) {
    uint32_t r;
    asm("cvt.rna.tf32.f32 %0, %1;" : "=r"(r) : "f"(f));
    return r;
}

__device__ __forceinline__ float ex2(float x) {
    float y;
    asm("ex2.approx.ftz.f32 %0, %1;" : "=f"(y) : "f"(x));
    return y;
}

// pack two f32 into f16x2 (register use only — validated in R8's PV path)
__device__ __forceinline__ uint32_t pack_f16(float lo, float hi) {
    uint32_t d;
    asm("cvt.rn.f16x2.f32 %0, %1, %2;" : "=r"(d) : "f"(hi), "f"(lo));
    return d;
}

__device__ __forceinline__ void mma_tf32(float c[4],
    uint32_t a0, uint32_t a1, uint32_t a2, uint32_t a3,
    uint32_t b0, uint32_t b1)
{
    asm volatile(
        "mma.sync.aligned.m16n8k8.row.col.f32.tf32.tf32.f32 "
        "{%0,%1,%2,%3}, {%4,%5,%6,%7}, {%8,%9}, {%0,%1,%2,%3};"
        : "+f"(c[0]), "+f"(c[1]), "+f"(c[2]), "+f"(c[3])
        : "r"(a0), "r"(a1), "r"(a2), "r"(a3), "r"(b0), "r"(b1));
}

__device__ __forceinline__ void mma_f16(float c[4],
    uint32_t a0, uint32_t a1, uint32_t a2, uint32_t a3,
    uint32_t b0, uint32_t b1)
{
    asm volatile(
        "mma.sync.aligned.m16n8k16.row.col.f32.f16.f16.f32 "
        "{%0,%1,%2,%3}, {%4,%5,%6,%7}, {%8,%9}, {%0,%1,%2,%3};"
        : "+f"(c[0]), "+f"(c[1]), "+f"(c[2]), "+f"(c[3])
        : "r"(a0), "r"(a1), "r"(a2), "r"(a3), "r"(b0), "r"(b1));
}

__device__ __forceinline__ void cp_async16(uint32_t smem_addr, const void* gptr) {
    asm volatile("cp.async.ca.shared.global [%0], [%1], 16;"
                 :: "r"(smem_addr), "l"(gptr));
}

// ---------------------------------------------------------------------------
// prep: x, w_qv, w_out -> tf32; ext_k -> fp16 (intrinsic stores only)
// ---------------------------------------------------------------------------
#define N4_X    (B_ * N_SEQ * DIM / 4)
#define N4_WQV  (DIM * 2 * INNER / 4)
#define N4_K    (HEADS * N_SEQ * DHEAD / 4)
#define N4_WOUT (DIM * DIM / 4)
#define N4_TOT  (N4_X + N4_WQV + N4_K + N4_WOUT)

__global__ void __launch_bounds__(256) cvt_all_kernel(
    const float* __restrict__ x, const float* __restrict__ wqv,
    const float* __restrict__ ek, const float* __restrict__ wout)
{
    int i = blockIdx.x * 256 + threadIdx.x;
    if (i < N4_X) {
        const float4 v = ((const float4*)x)[i];
        uint4 u;
        u.x = f2tf32(v.x); u.y = f2tf32(v.y);
        u.z = f2tf32(v.z); u.w = f2tf32(v.w);
        ((uint4*)g_x32)[i] = u;
    } else if (i < N4_X + N4_WQV) {
        i -= N4_X;
        const float4 v = ((const float4*)wqv)[i];
        uint4 u;
        u.x = f2tf32(v.x); u.y = f2tf32(v.y);
        u.z = f2tf32(v.z); u.w = f2tf32(v.w);
        ((uint4*)g_wqv32)[i] = u;
    } else if (i < N4_X + N4_WQV + N4_K) {
        i -= N4_X + N4_WQV;
        const float4 v = ((const float4*)ek)[i];
        __half2* dst = (__half2*)g_k16 + i * 2;
        dst[0] = __halves2half2(__float2half_rn(v.x), __float2half_rn(v.y));
        dst[1] = __halves2half2(__float2half_rn(v.z), __float2half_rn(v.w));
    } else {
        i -= N4_X + N4_WQV + N4_K;
        const float4 v = ((const float4*)wout)[i];
        uint4 u;
        u.x = f2tf32(v.x); u.y = f2tf32(v.y);
        u.z = f2tf32(v.z); u.w = f2tf32(v.w);
        ((uint4*)g_wout32)[i] = u;
    }
}

// ---------------------------------------------------------------------------
// tf32 GEMM — R8 verbatim mainloop (single-buffer + reg prefetch).
// EPI=0: q (fp16, pre-scaled, intrinsic stores) -> g_q16, v (fp16 [d][m]) -> g_vt
// EPI=1: A=g_att (tf32), W=g_wout32, +bias -> out (fp32)
// ---------------------------------------------------------------------------
#define GBM 128
#define GBN 64
#define GBK 32
#define SA_STR 36
#define SB2_STR 72

template<int EPI>
__global__ void __launch_bounds__(256) gemm_tf32_kernel(
    const float* __restrict__ bias, float* __restrict__ out, int N)
{
    __shared__ uint32_t sA[GBM * SA_STR];
    __shared__ uint32_t sB[GBK * SB2_STR];

    const float* A = (EPI == 1) ? (const float*)g_att : (const float*)g_x32;
    const float* W = (EPI == 1) ? (const float*)g_wout32 : (const float*)g_wqv32;

    const int tid  = threadIdx.x;
    const int wid  = tid >> 5, lane = tid & 31;
    const int lr   = lane >> 2, lc = lane & 3;
    const int wm   = wid >> 1, wn = wid & 1;
    const int m0   = wm * 32, n0w = wn * 32;
    const int row0 = blockIdx.y * GBM;
    const int col0 = blockIdx.x * GBN;

    const int a_row = tid >> 3, a_k4 = tid & 7;
    const int b_kr = tid >> 4, b_n4 = tid & 15;

    float acc[2][4][4];
    #pragma unroll
    for (int i = 0; i < 2; ++i)
        #pragma unroll
        for (int j = 0; j < 4; ++j)
            #pragma unroll
            for (int e = 0; e < 4; ++e) acc[i][j][e] = 0.f;

    uint4 ra[4], rb[2];
    #pragma unroll
    for (int it = 0; it < 4; ++it)
        ra[it] = *(const uint4*)(A + (row0 + a_row + 32 * it) * DIM + a_k4 * 4);
    #pragma unroll
    for (int it = 0; it < 2; ++it)
        rb[it] = *(const uint4*)(W + (b_kr + 16 * it) * N + col0 + b_n4 * 4);

    for (int k0 = 0; k0 < DIM; k0 += GBK) {
        #pragma unroll
        for (int it = 0; it < 4; ++it)
            *(uint4*)(sA + (a_row + 32 * it) * SA_STR + a_k4 * 4) = ra[it];
        #pragma unroll
        for (int it = 0; it < 2; ++it)
            *(uint4*)(sB + (b_kr + 16 * it) * SB2_STR + b_n4 * 4) = rb[it];
        __syncthreads();

        if (k0 + GBK < DIM) {
            #pragma unroll
            for (int it = 0; it < 4; ++it)
                ra[it] = *(const uint4*)(A + (row0 + a_row + 32 * it) * DIM + k0 + GBK + a_k4 * 4);
            #pragma unroll
            for (int it = 0; it < 2; ++it)
                rb[it] = *(const uint4*)(W + (k0 + GBK + b_kr + 16 * it) * N + col0 + b_n4 * 4);
        }

        #pragma unroll
        for (int kk = 0; kk < 4; ++kk) {
            const int kb = kk * 8;
            uint32_t af[2][4], bf[4][2];
            #pragma unroll
            for (int i = 0; i < 2; ++i) {
                const int mr = m0 + i * 16 + lr;
                af[i][0] = sA[ mr      * SA_STR + kb + lc    ];
                af[i][1] = sA[(mr + 8) * SA_STR + kb + lc    ];
                af[i][2] = sA[ mr      * SA_STR + kb + lc + 4];
                af[i][3] = sA[(mr + 8) * SA_STR + kb + lc + 4];
            }
            #pragma unroll
            for (int j = 0; j < 4; ++j) {
                const int nc = n0w + j * 8 + lr;
                bf[j][0] = sB[(kb + lc    ) * SB2_STR + nc];
                bf[j][1] = sB[(kb + lc + 4) * SB2_STR + nc];
            }
            #pragma unroll
            for (int i = 0; i < 2; ++i)
                #pragma unroll
                for (int j = 0; j < 4; ++j)
                    mma_tf32(acc[i][j], af[i][0], af[i][1], af[i][2], af[i][3],
                             bf[j][0], bf[j][1]);
        }
        __syncthreads();
    }

    if (EPI == 0) {
        if (col0 < INNER) {
            // q: fp16, pre-scaled by SCALE_C — INTRINSIC stores
            const int h = col0 >> 6;
            #pragma unroll
            for (int i = 0; i < 2; ++i) {
                #pragma unroll
                for (int half = 0; half < 2; ++half) {
                    const int rg = row0 + m0 + i * 16 + lr + half * 8;
                    const int bb = rg >> 10, nn = rg & 1023;
                    __half* rp = g_q16 + ((((bb * HEADS + h) << 10) + nn) << 6);
                    #pragma unroll
                    for (int j = 0; j < 4; ++j) {
                        const int d = n0w + j * 8 + lc * 2;
                        __half2 h2 = __halves2half2(
                            __float2half_rn(acc[i][j][half * 2]     * SCALE_C),
                            __float2half_rn(acc[i][j][half * 2 + 1] * SCALE_C));
                        *(__half2*)(rp + d) = h2;
                    }
                }
            }
        } else {
            // v: fp16, transposed [b,h,d,m] — scalar stores (R8-validated)
            const int h = (col0 - INNER) >> 6;
            #pragma unroll
            for (int i = 0; i < 2; ++i) {
                #pragma unroll
                for (int half = 0; half < 2; ++half) {
                    const int rg = row0 + m0 + i * 16 + lr + half * 8;
                    const int bb = rg >> 10, nn = rg & 1023;
                    __half* vp = g_vt + (((bb * HEADS + h) << 6) << 10) + nn;
                    #pragma unroll
                    for (int j = 0; j < 4; ++j) {
                        const int d = n0w + j * 8 + lc * 2;
                        vp[ d      << 10] = __float2half_rn(acc[i][j][half * 2]);
                        vp[(d + 1) << 10] = __float2half_rn(acc[i][j][half * 2 + 1]);
                    }
                }
            }
        }
    } else {
        #pragma unroll
        for (int i = 0; i < 2; ++i) {
            #pragma unroll
            for (int half = 0; half < 2; ++half) {
                const int rg = row0 + m0 + i * 16 + lr + half * 8;
                float* rp = out + rg * DIM + col0;
                #pragma unroll
                for (int j = 0; j < 4; ++j) {
                    const int c = n0w + j * 8 + lc * 2;
                    float2 o;
                    o.x = acc[i][j][half * 2]     + bias[col0 + c];
                    o.y = acc[i][j][half * 2 + 1] + bias[col0 + c + 1];
                    *(float2*)(rp + c) = o;
                }
            }
        }
    }
}

// ---------------------------------------------------------------------------
// Fused attention — R8 structure with QK switched to fp16 m16n8k16.
// fp16 Q (pre-scaled) and fp16 K; ex2.approx softmax (no max);
// register fp16 P; fp16 PV vs pre-transposed V; writes g_att tf32 float.
// ---------------------------------------------------------------------------
#define BM 64
#define BN 64
#define SK_STR 36     // 32 payload uint32 (64 halves) + 4 pad
#define SVT_STR 36

__global__ void __launch_bounds__(128) attn_mma_kernel(
    const float* __restrict__ BIAS)
{
    __shared__ alignas(16) uint32_t sK [BN * SK_STR];     // K tile fp16 (also Q staging)
    __shared__ alignas(16) uint32_t sVt[DHEAD * SVT_STR]; // V^T tile fp16

    const int tid  = threadIdx.x;
    const int wid  = tid >> 5, lane = tid & 31;
    const int bb = blockIdx.x, qt = blockIdx.y, h = blockIdx.z;

    const int lr = lane >> 2;
    const int lc = lane & 3;
    const int r0 = wid * 16 + lr;

    const uint32_t sk_u  = (uint32_t)__cvta_generic_to_shared(sK);
    const uint32_t svt_u = (uint32_t)__cvta_generic_to_shared(sVt);

    // ---- stage Q (fp16, pre-scaled) through sK, pull A-fragments
    const uint4* Qg = (const uint4*)(g_q16 + (((bb * HEADS + h) << 10) + qt * BM) * 64);
    #pragma unroll
    for (int i = tid; i < BM * 8; i += 128) {       // 512 uint4
        const int row = i >> 3, c = i & 7;
        *(uint4*)(sK + row * SK_STR + c * 4) = Qg[row * 8 + c];
    }
    __syncthreads();

    uint32_t qa[4][4];
    #pragma unroll
    for (int ks = 0; ks < 4; ++ks) {
        qa[ks][0] = sK[ r0      * SK_STR + ks * 8 + lc    ];
        qa[ks][1] = sK[(r0 + 8) * SK_STR + ks * 8 + lc    ];
        qa[ks][2] = sK[ r0      * SK_STR + ks * 8 + lc + 4];
        qa[ks][3] = sK[(r0 + 8) * SK_STR + ks * 8 + lc + 4];
    }
    __syncthreads();   // done with sK as Q staging

    float acc[8][4];
    #pragma unroll
    for (int nt = 0; nt < 8; ++nt)
        #pragma unroll
        for (int j = 0; j < 4; ++j) acc[nt][j] = 0.f;

    float l_lo = 0.f, l_hi = 0.f;

    const uint4* Kg = (const uint4*)(g_k16 + ((h << 10) << 6));
    const __half* Vtg = g_vt + (((bb * HEADS + h) << 6) << 10);
    const float* Bg = BIAS + (((h << 10) + qt * BM) << 10);
    const float* bl = Bg +  r0      * N_SEQ + lc * 2;
    const float* bh = Bg + (r0 + 8) * N_SEQ + lc * 2;

    for (int mt = 0; mt < N_SEQ; mt += BN) {
        // ---- cp.async: K (fp16) and V^T (fp16)
        #pragma unroll
        for (int i = tid; i < BN * 8; i += 128) {
            const int row = i >> 3, c = i & 7;
            cp_async16(sk_u + (row * SK_STR + c * 4) * 4, Kg + (mt + row) * 8 + c);
        }
        #pragma unroll
        for (int i = tid; i < DHEAD * 8; i += 128) {
            const int row = i >> 3, c = i & 7;
            cp_async16(svt_u + (row * SVT_STR + c * 4) * 4, Vtg + (row << 10) + mt + c * 8);
        }
        // ---- bias into registers (overlaps cp.async)
        float2 blo[8], bhi[8];
        #pragma unroll
        for (int nt = 0; nt < 8; ++nt) {
            blo[nt] = *(const float2*)(bl + mt + nt * 8);
            bhi[nt] = *(const float2*)(bh + mt + nt * 8);
        }
        asm volatile("cp.async.wait_all;" ::: "memory");
        __syncthreads();

        // ---- S = Q @ K^T (fp16 m16n8k16, fp32 accum)
        float s[8][4];
        #pragma unroll
        for (int nt = 0; nt < 8; ++nt)
            #pragma unroll
            for (int j = 0; j < 4; ++j) s[nt][j] = 0.f;

        #pragma unroll
        for (int nt = 0; nt < 8; ++nt) {
            const int n0 = nt * 8;
            #pragma unroll
            for (int ks = 0; ks < 4; ++ks) {
                const uint32_t b0 = sK[(n0 + lr) * SK_STR + ks * 8 + lc    ];
                const uint32_t b1 = sK[(n0 + lr) * SK_STR + ks * 8 + lc + 4];
                mma_f16(s[nt], qa[ks][0], qa[ks][1], qa[ks][2], qa[ks][3], b0, b1);
            }
        }

        // ---- p = exp2(s + bias*scale); pack fp16 in regs (A-frag layout)
        uint32_t pa[8][2];
        #pragma unroll
        for (int nt = 0; nt < 8; ++nt) {
            const float p0 = ex2(fmaf(blo[nt].x, SCALE_C, s[nt][0]));
            const float p1 = ex2(fmaf(blo[nt].y, SCALE_C, s[nt][1]));
            const float p2 = ex2(fmaf(bhi[nt].x, SCALE_C, s[nt][2]));
            const float p3 = ex2(fmaf(bhi[nt].y, SCALE_C, s[nt][3]));
            l_lo += p0 + p1;
            l_hi += p2 + p3;
            pa[nt][0] = pack_f16(p0, p1);   // rows lr
            pa[nt][1] = pack_f16(p2, p3);   // rows lr+8
        }

        // ---- acc += P @ V (fp16 m16n8k16, P register-direct)
        #pragma unroll
        for (int ks = 0; ks < 4; ++ks) {
            const uint32_t a0 = pa[2 * ks    ][0];
            const uint32_t a1 = pa[2 * ks    ][1];
            const uint32_t a2 = pa[2 * ks + 1][0];
            const uint32_t a3 = pa[2 * ks + 1][1];
            #pragma unroll
            for (int nt = 0; nt < 8; ++nt) {
                const uint32_t* vrow = sVt + (nt * 8 + lr) * SVT_STR + ks * 8;
                mma_f16(acc[nt], a0, a1, a2, a3, vrow[lc], vrow[lc + 4]);
            }
        }
        __syncthreads();   // all sK/sVt reads done before next tile's cp.async
    }

    // ---- row-sum reduce, normalize, write tf32 float (R8-validated format)
    l_lo += __shfl_xor_sync(0xffffffffu, l_lo, 1);
    l_lo += __shfl_xor_sync(0xffffffffu, l_lo, 2);
    l_hi += __shfl_xor_sync(0xffffffffu, l_hi, 1);
    l_hi += __shfl_xor_sync(0xffffffffu, l_hi, 2);
    const float inv_lo = 1.f / l_lo;
    const float inv_hi = 1.f / l_hi;
    const int n_lo = qt * BM + r0;
    float* outb = g_att + ((bb << 10) * INNER) + (h << 6);
    #pragma unroll
    for (int nt = 0; nt < 8; ++nt) {
        const int d = nt * 8 + lc * 2;
        float2 olo, ohi;
        olo.x = __int_as_float(f2tf32(acc[nt][0] * inv_lo));
        olo.y = __int_as_float(f2tf32(acc[nt][1] * inv_lo));
        ohi.x = __int_as_float(f2tf32(acc[nt][2] * inv_hi));
        ohi.y = __int_as_float(f2tf32(acc[nt][3] * inv_hi));
        *(float2*)(outb + n_lo       * INNER + d) = olo;
        *(float2*)(outb + (n_lo + 8) * INNER + d) = ohi;
    }
}

// ---------------------------------------------------------------------------
extern "C" void kernel_launch(void* const* d_in, const int* in_sizes, int n_in,
                              void* d_out, int out_size)
{
    const float* x        = (const float*)d_in[0];
    const float* w_qv     = (const float*)d_in[1];
    const float* ext_k    = (const float*)d_in[2];
    const float* ext_bias = (const float*)d_in[3];
    const float* w_out    = (const float*)d_in[4];
    const float* b_out    = (const float*)d_in[5];
    float* out = (float*)d_out;

    cvt_all_kernel<<<N4_TOT / 256, 256>>>(x, w_qv, ext_k, w_out);
    gemm_tf32_kernel<0><<<dim3(2 * INNER / GBN, B_ * N_SEQ / GBM), 256>>>(
        nullptr, nullptr, 2 * INNER);
    attn_mma_kernel<<<dim3(B_, N_SEQ / BM, HEADS), 128>>>(ext_bias);
    gemm_tf32_kernel<1><<<dim3(DIM / GBN, B_ * N_SEQ / GBM), 256>>>(
        b_out, out, DIM);
}